// round 4
// baseline (speedup 1.0000x reference)
#include <cuda_runtime.h>
#include <float.h>

#define Bg   64
#define Lg   1024
#define Kn   16
#define INF_ 128
#define OUTF 128
#define Sd   4
#define FLRd 64
#define Ntot (Bg * Lg)

typedef unsigned long long ull_t;

// Blackwell packed fp32x2 FMA (2 independent fp32 lanes per instruction).
#define FMA2(d, a, b, c) \
    asm("fma.rn.f32x2 %0, %1, %2, %3;" : "=l"(d) : "l"(a), "l"(b), "l"(c))
#define PACK_DUP(d, f) \
    do { unsigned _u = __float_as_uint(f); \
         asm("mov.b64 %0, {%1, %1};" : "=l"(d) : "r"(_u)); } while (0)
#define UNPACK2(lo, hi, v) \
    asm("mov.b64 {%0, %1}, %2;" : "=r"(lo), "=r"(hi) : "l"(v))

// ---- scratch (static device globals; no allocation allowed) ----
__device__ float g_s[Ntot * Sd];          //  1 MB   learned kNN space
__device__ float g_h[Ntot * FLRd];        // 16 MB   propagated features
__device__ float g_w[Ntot * Kn];          //  4 MB   edge weights
__device__ int   g_id[Ntot * Kn];         //  4 MB   neighbor indices (global)
__device__ float g_agg[Ntot * 2 * FLRd];  // 32 MB   [mean(64) | max(64)] per node

// ============================================================
// Kernel 1: fused s/h embedding, FFMA2 over the K dimension.
//   Wt[c][k] transposed in smem (pitch 130 -> 8B-aligned rows),
//   so {W[k,c],W[k+1,c]} and {x[r,k],x[r,k+1]} are single LDS.64.
//   Accumulators hold even/odd-k halves, summed at the end.
// ============================================================
#define WT_P 130

__global__ __launch_bounds__(256) void k_embed(
    const float* __restrict__ x,
    const float* __restrict__ Ws, const float* __restrict__ bs,
    const float* __restrict__ Wh, const float* __restrict__ bh)
{
    __shared__ float Wt[68][WT_P];    // 35.4 KB, Wt[c][k]
    __shared__ float xs[32][128];     // 16 KB

    int t = threadIdx.x;
    for (int i = t; i < 128 * 68; i += 256) {
        int k = i / 68, c = i % 68;
        Wt[c][k] = (c < 64) ? Wh[k * 64 + c] : Ws[k * 4 + (c - 64)];
    }

    int base_row = blockIdx.x * 32;
    for (int i = t; i < 1024; i += 256) {
        int r = i >> 5, q = i & 31;
        ((float4*)&xs[r][0])[q] = ((const float4*)(x + (size_t)(base_row + r) * 128))[q];
    }
    __syncthreads();

    int warp = t >> 5, lane = t & 31;
    int r0 = warp * 4;

    const ull_t* w0p = (const ull_t*)&Wt[lane][0];
    const ull_t* w1p = (const ull_t*)&Wt[32 + lane][0];
    const ull_t* w2p = (const ull_t*)&Wt[64 + (lane & 3)][0];   // in-bounds for all lanes
    const ull_t* xp[4];
#pragma unroll
    for (int r = 0; r < 4; r++) xp[r] = (const ull_t*)&xs[r0 + r][0];

    ull_t A0[4] = {0ull, 0ull, 0ull, 0ull};
    ull_t A1[4] = {0ull, 0ull, 0ull, 0ull};
    ull_t A2[4] = {0ull, 0ull, 0ull, 0ull};

#pragma unroll 4
    for (int kh = 0; kh < 64; kh++) {          // 2 k per step
        ull_t w0 = w0p[kh];
        ull_t w1 = w1p[kh];
        ull_t w2 = w2p[kh];
#pragma unroll
        for (int r = 0; r < 4; r++) {
            ull_t xv = xp[r][kh];
            FMA2(A0[r], xv, w0, A0[r]);
            FMA2(A1[r], xv, w1, A1[r]);
            FMA2(A2[r], xv, w2, A2[r]);
        }
    }

    float bh0 = bh[lane], bh1 = bh[32 + lane];
#pragma unroll
    for (int r = 0; r < 4; r++) {
        unsigned lo, hi;
        int row = base_row + r0 + r;
        UNPACK2(lo, hi, A0[r]);
        g_h[(size_t)row * 64 + lane] =
            __uint_as_float(lo) + __uint_as_float(hi) + bh0;
        UNPACK2(lo, hi, A1[r]);
        g_h[(size_t)row * 64 + 32 + lane] =
            __uint_as_float(lo) + __uint_as_float(hi) + bh1;
        UNPACK2(lo, hi, A2[r]);
        if (lane < 4)
            g_s[(size_t)row * 4 + lane] =
                __uint_as_float(lo) + __uint_as_float(hi) + bs[lane];
    }
}

// ============================================================
// Kernel 2: per-graph kNN, K=16 smallest d2 (self included).
//   (d2,index) packed in ONE float: low 10 mantissa bits = j.
//   Sorted-insert = 2 FMNMX per stage. Exact d2 recomputed for
//   the 16 winners for the edge weights.
// ============================================================
__global__ __launch_bounds__(512) void k_knn()
{
    __shared__ float4 sg[Lg];
    int b = blockIdx.x;
    int base = b * Lg;

    const float4* sp = (const float4*)(g_s + (size_t)base * 4);
    for (int i = threadIdx.x; i < Lg; i += blockDim.x) sg[i] = sp[i];
    __syncthreads();

    int i = blockIdx.y * blockDim.x + threadIdx.x;
    float4 si = sg[i];

    float lst[Kn];
#pragma unroll
    for (int tt = 0; tt < Kn; tt++) lst[tt] = FLT_MAX;

#pragma unroll 4
    for (int j = 0; j < Lg; j++) {
        float4 sj = sg[j];
        float dx = si.x - sj.x, dy = si.y - sj.y;
        float dz = si.z - sj.z, dw = si.w - sj.w;
        float d2 = dx * dx + dy * dy;
        d2 = fmaf(dz, dz, d2);
        d2 = fmaf(dw, dw, d2);
        float pv = __uint_as_float((__float_as_uint(d2) & 0xFFFFFC00u) | (unsigned)j);
        if (pv < lst[Kn - 1]) {
            float v = pv;
#pragma unroll
            for (int tt = 0; tt < Kn; tt++) {
                float lo = fminf(v, lst[tt]);
                v       = fmaxf(v, lst[tt]);
                lst[tt] = lo;
            }
        }
    }

    int   oid[Kn];
    float ow [Kn];
#pragma unroll
    for (int tt = 0; tt < Kn; tt++) {
        int j = (int)(__float_as_uint(lst[tt]) & 1023u);
        float4 sj = sg[j];
        float dx = si.x - sj.x, dy = si.y - sj.y;
        float dz = si.z - sj.z, dw = si.w - sj.w;
        float d2 = dx * dx + dy * dy;
        d2 = fmaf(dz, dz, d2);
        d2 = fmaf(dw, dw, d2);
        oid[tt] = base + j;
        ow [tt] = __expf(-10.f * d2);
    }
    int4*   idp = (int4*)  (g_id + (size_t)(base + i) * Kn);
    float4* wp  = (float4*)(g_w  + (size_t)(base + i) * Kn);
#pragma unroll
    for (int q = 0; q < 4; q++) {
        idp[q] = make_int4(oid[q*4], oid[q*4+1], oid[q*4+2], oid[q*4+3]);
        wp [q] = make_float4(ow[q*4], ow[q*4+1], ow[q*4+2], ow[q*4+3]);
    }
}

// ============================================================
// Kernel 3: warp-per-node gather + mean/max aggregation.
// ============================================================
__global__ __launch_bounds__(256) void k_agg()
{
    int node = (blockIdx.x * blockDim.x + threadIdx.x) >> 5;
    int lane = threadIdx.x & 31;
    if (node >= Ntot) return;

    int   myid = 0;
    float mywt = 0.f;
    if (lane < Kn) {
        myid = g_id[(size_t)node * Kn + lane];
        mywt = g_w [(size_t)node * Kn + lane];
    }

    float s0 = 0.f, s1 = 0.f, m0 = -FLT_MAX, m1 = -FLT_MAX;
#pragma unroll
    for (int nb = 0; nb < Kn; nb++) {
        int   id = __shfl_sync(0xffffffffu, myid, nb);
        float wt = __shfl_sync(0xffffffffu, mywt, nb);
        float v0 = __ldg(&g_h[(size_t)id * 64 + lane])      * wt;
        float v1 = __ldg(&g_h[(size_t)id * 64 + 32 + lane]) * wt;
        s0 += v0;  s1 += v1;
        m0 = fmaxf(m0, v0);  m1 = fmaxf(m1, v1);
    }
    float* ap = g_agg + (size_t)node * 128;
    ap[lane]      = s0 * (1.f / 16.f);
    ap[32 + lane] = s1 * (1.f / 16.f);
    ap[64 + lane] = m0;
    ap[96 + lane] = m1;
}

// ============================================================
// Kernel 4: out = relu([x | agg] @ W_out + b_out)
//   R1 single-buffer 128x128x32 structure, inner loop in packed
//   fp32x2 FMA: acc = 8 rows x 4 col-pairs of f32x2.
//   __launch_bounds__(256,2) keeps 2 blocks/SM resident.
// ============================================================
#define BM 128
#define BN 128
#define BK 32

__global__ __launch_bounds__(256, 2) void k_out(
    const float* __restrict__ x,
    const float* __restrict__ Wout,
    const float* __restrict__ bout,
    float* __restrict__ out)
{
    __shared__ float As[BK][BM + 4];
    __shared__ float Bs[BK][BN];

    int t = threadIdx.x;
    int block_row = blockIdx.x * BM;
    int tx = t & 15, ty = t >> 4;     // 16x16 threads, 8x8 outputs each

    ull_t acc2[8][4];
#pragma unroll
    for (int i = 0; i < 8; i++)
#pragma unroll
        for (int jp = 0; jp < 4; jp++) acc2[i][jp] = 0ull;   // {0.f, 0.f}

    for (int kt = 0; kt < 256; kt += BK) {
        const float* Abase = (kt < 128) ? (x + kt) : (g_agg + (kt - 128));

        // A tile: 128 rows x 32 k, transposed into As[k][row]
        {
            int r  = t >> 1;
            int kc = (t & 1) * 16;
            const float4* src = (const float4*)(Abase + (size_t)(block_row + r) * 128 + kc);
#pragma unroll
            for (int i = 0; i < 4; i++) {
                float4 v = src[i];
                As[kc + i * 4 + 0][r] = v.x;
                As[kc + i * 4 + 1][r] = v.y;
                As[kc + i * 4 + 2][r] = v.z;
                As[kc + i * 4 + 3][r] = v.w;
            }
        }
        // B tile: 32 rows x 128 cols
        {
            const float4* src = (const float4*)(Wout + (size_t)kt * 128);
#pragma unroll
            for (int i = 0; i < 4; i++) {
                int lin  = t + i * 256;
                int row  = lin >> 5;
                int col4 = lin & 31;
                ((float4*)&Bs[row][0])[col4] = src[lin];
            }
        }
        __syncthreads();

#pragma unroll
        for (int kk = 0; kk < BK; kk++) {
            // a: 8 contiguous floats; b: 4 contiguous f32x2 pairs
            const float4* ap4 = (const float4*)&As[kk][ty * 8];
            float4 av0 = ap4[0], av1 = ap4[1];
            float a[8] = {av0.x, av0.y, av0.z, av0.w, av1.x, av1.y, av1.z, av1.w};
            const ull_t* bp = (const ull_t*)&Bs[kk][tx * 8];
            ull_t b2[4];
#pragma unroll
            for (int jp = 0; jp < 4; jp++) b2[jp] = bp[jp];

            ull_t a2[8];
#pragma unroll
            for (int i = 0; i < 8; i++) PACK_DUP(a2[i], a[i]);
#pragma unroll
            for (int i = 0; i < 8; i++)
#pragma unroll
                for (int jp = 0; jp < 4; jp++)
                    FMA2(acc2[i][jp], a2[i], b2[jp], acc2[i][jp]);
        }
        __syncthreads();
    }

    float bias[8];
#pragma unroll
    for (int j = 0; j < 8; j++) bias[j] = bout[tx * 8 + j];

#pragma unroll
    for (int i = 0; i < 8; i++) {
        int row = block_row + ty * 8 + i;
        float v[8];
#pragma unroll
        for (int jp = 0; jp < 4; jp++) {
            unsigned lo, hi;
            UNPACK2(lo, hi, acc2[i][jp]);
            v[jp * 2 + 0] = fmaxf(__uint_as_float(lo) + bias[jp * 2 + 0], 0.f);
            v[jp * 2 + 1] = fmaxf(__uint_as_float(hi) + bias[jp * 2 + 1], 0.f);
        }
        float4* dst = (float4*)(out + (size_t)row * 128 + tx * 8);
        dst[0] = make_float4(v[0], v[1], v[2], v[3]);
        dst[1] = make_float4(v[4], v[5], v[6], v[7]);
    }
}

// ============================================================
extern "C" void kernel_launch(void* const* d_in, const int* in_sizes, int n_in,
                              void* d_out, int out_size)
{
    const float* x    = (const float*)d_in[0];
    const float* Ws   = (const float*)d_in[1];
    const float* bs   = (const float*)d_in[2];
    const float* Wh   = (const float*)d_in[3];
    const float* bh   = (const float*)d_in[4];
    const float* Wout = (const float*)d_in[5];
    const float* bout = (const float*)d_in[6];
    // d_in[7] = batch (int64): contiguous equal-size graphs; layout implicit.
    float* out = (float*)d_out;

    k_embed<<<Ntot / 32, 256>>>(x, Ws, bs, Wh, bh);
    k_knn<<<dim3(Bg, 2), 512>>>();
    k_agg<<<Ntot / 8, 256>>>();
    k_out<<<Ntot / BM, 256>>>(x, Wout, bout, out);
}

// round 7
// speedup vs baseline: 1.9189x; 1.9189x over previous
#include <cuda_runtime.h>
#include <cuda_bf16.h>
#include <cstdint>
#include <float.h>

#define Bg   64
#define Lg   1024
#define Kn   16
#define Ntot (Bg * Lg)

// ---- scratch (static device globals; no allocation allowed) ----
__device__ float g_s[Ntot * 4];            //  1 MB   learned kNN space
__device__ float g_h[Ntot * 64];           // 16 MB   propagated features
__device__ float g_w[Ntot * Kn];           //  4 MB   edge weights
__device__ int   g_id[Ntot * Kn];          //  4 MB   neighbor indices
__device__ float g_agg[Ntot * 128];        // 32 MB   [mean(64) | max(64)]
__device__ __nv_bfloat16 g_Bhi[128 * 256]; // 64 KB   W_out^T hi  (layout [n][k])
__device__ __nv_bfloat16 g_Blo[128 * 256]; // 64 KB   W_out^T lo

__device__ __forceinline__ uint32_t smem_u32(const void* p) {
    uint32_t a;
    asm("{ .reg .u64 t; cvta.to.shared.u64 t, %1; cvt.u32.u64 %0, t; }"
        : "=r"(a) : "l"(p));
    return a;
}

#define LDSM_X4(r0, r1, r2, r3, addr) \
    asm volatile("ldmatrix.sync.aligned.m8n8.x4.shared.b16 {%0,%1,%2,%3}, [%4];" \
                 : "=r"(r0), "=r"(r1), "=r"(r2), "=r"(r3) : "r"(addr))

#define MMA16816(c, a, b) \
    asm volatile("mma.sync.aligned.m16n8k16.row.col.f32.bf16.bf16.f32 " \
                 "{%0,%1,%2,%3}, {%4,%5,%6,%7}, {%8,%9}, {%0,%1,%2,%3};" \
                 : "+f"((c)[0]), "+f"((c)[1]), "+f"((c)[2]), "+f"((c)[3]) \
                 : "r"((a)[0]), "r"((a)[1]), "r"((a)[2]), "r"((a)[3]), \
                   "r"((b)[0]), "r"((b)[1]))

__device__ __forceinline__ unsigned pack_bf2(__nv_bfloat16 a, __nv_bfloat16 b) {
    __nv_bfloat162 p = __halves2bfloat162(a, b);
    return *reinterpret_cast<unsigned*>(&p);
}

// ============================================================
// Kernel 1: fused s/h embedding (R3 proven).
// ============================================================
__global__ __launch_bounds__(256) void k_embed(
    const float* __restrict__ x,
    const float* __restrict__ Ws, const float* __restrict__ bs,
    const float* __restrict__ Wh, const float* __restrict__ bh)
{
    __shared__ float Wc[128 * 68 + 32];
    __shared__ float xs[32][128];

    int t = threadIdx.x;
    for (int i = t; i < 128 * 68; i += 256) {
        int k = i / 68, c = i % 68;
        Wc[i] = (c < 64) ? Wh[k * 64 + c] : Ws[k * 4 + (c - 64)];
    }
    int base_row = blockIdx.x * 32;
    for (int i = t; i < 1024; i += 256) {
        int r = i >> 5, q = i & 31;
        ((float4*)&xs[r][0])[q] = ((const float4*)(x + (size_t)(base_row + r) * 128))[q];
    }
    __syncthreads();

    int warp = t >> 5, lane = t & 31;
    int r0 = warp * 4;
    float a0[4] = {0, 0, 0, 0}, a1[4] = {0, 0, 0, 0}, a2[4] = {0, 0, 0, 0};

#pragma unroll 4
    for (int k = 0; k < 128; k++) {
        float w0 = Wc[k * 68 + lane];
        float w1 = Wc[k * 68 + 32 + lane];
        float w2 = Wc[k * 68 + 64 + lane];
#pragma unroll
        for (int r = 0; r < 4; r++) {
            float xv = xs[r0 + r][k];
            a0[r] = fmaf(xv, w0, a0[r]);
            a1[r] = fmaf(xv, w1, a1[r]);
            a2[r] = fmaf(xv, w2, a2[r]);
        }
    }
    float bh0 = bh[lane], bh1 = bh[32 + lane];
#pragma unroll
    for (int r = 0; r < 4; r++) {
        int row = base_row + r0 + r;
        g_h[(size_t)row * 64 + lane]      = a0[r] + bh0;
        g_h[(size_t)row * 64 + 32 + lane] = a1[r] + bh1;
        if (lane < 4) g_s[(size_t)row * 4 + lane] = a2[r] + bs[lane];
    }
}

// ============================================================
// Kernel 2: per-graph kNN (R3 proven; packed (d2,idx) FMNMX chain).
// ============================================================
__global__ __launch_bounds__(512) void k_knn()
{
    __shared__ float4 sg[Lg];
    int b = blockIdx.x;
    int base = b * Lg;

    const float4* sp = (const float4*)(g_s + (size_t)base * 4);
    for (int i = threadIdx.x; i < Lg; i += blockDim.x) sg[i] = sp[i];
    __syncthreads();

    int i = blockIdx.y * blockDim.x + threadIdx.x;
    float4 si = sg[i];

    float lst[Kn];
#pragma unroll
    for (int tt = 0; tt < Kn; tt++) lst[tt] = FLT_MAX;

#pragma unroll 4
    for (int j = 0; j < Lg; j++) {
        float4 sj = sg[j];
        float dx = si.x - sj.x, dy = si.y - sj.y;
        float dz = si.z - sj.z, dw = si.w - sj.w;
        float d2 = dx * dx + dy * dy;
        d2 = fmaf(dz, dz, d2);
        d2 = fmaf(dw, dw, d2);
        float pv = __uint_as_float((__float_as_uint(d2) & 0xFFFFFC00u) | (unsigned)j);
        if (pv < lst[Kn - 1]) {
            float v = pv;
#pragma unroll
            for (int tt = 0; tt < Kn; tt++) {
                float lo = fminf(v, lst[tt]);
                v       = fmaxf(v, lst[tt]);
                lst[tt] = lo;
            }
        }
    }

    int   oid[Kn];
    float ow [Kn];
#pragma unroll
    for (int tt = 0; tt < Kn; tt++) {
        int j = (int)(__float_as_uint(lst[tt]) & 1023u);
        float4 sj = sg[j];
        float dx = si.x - sj.x, dy = si.y - sj.y;
        float dz = si.z - sj.z, dw = si.w - sj.w;
        float d2 = dx * dx + dy * dy;
        d2 = fmaf(dz, dz, d2);
        d2 = fmaf(dw, dw, d2);
        oid[tt] = base + j;
        ow [tt] = __expf(-10.f * d2);
    }
    int4*   idp = (int4*)  (g_id + (size_t)(base + i) * Kn);
    float4* wp  = (float4*)(g_w  + (size_t)(base + i) * Kn);
#pragma unroll
    for (int q = 0; q < 4; q++) {
        idp[q] = make_int4(oid[q*4], oid[q*4+1], oid[q*4+2], oid[q*4+3]);
        wp [q] = make_float4(ow[q*4], ow[q*4+1], ow[q*4+2], ow[q*4+3]);
    }
}

// ============================================================
// Kernel 3: warp-per-node gather + mean/max (R3 proven).
// ============================================================
__global__ __launch_bounds__(256) void k_agg()
{
    int node = (blockIdx.x * blockDim.x + threadIdx.x) >> 5;
    int lane = threadIdx.x & 31;
    if (node >= Ntot) return;

    int   myid = 0;
    float mywt = 0.f;
    if (lane < Kn) {
        myid = g_id[(size_t)node * Kn + lane];
        mywt = g_w [(size_t)node * Kn + lane];
    }
    float s0 = 0.f, s1 = 0.f, m0 = -FLT_MAX, m1 = -FLT_MAX;
#pragma unroll
    for (int nb = 0; nb < Kn; nb++) {
        int   id = __shfl_sync(0xffffffffu, myid, nb);
        float wt = __shfl_sync(0xffffffffu, mywt, nb);
        float v0 = __ldg(&g_h[(size_t)id * 64 + lane])      * wt;
        float v1 = __ldg(&g_h[(size_t)id * 64 + 32 + lane]) * wt;
        s0 += v0;  s1 += v1;
        m0 = fmaxf(m0, v0);  m1 = fmaxf(m1, v1);
    }
    float* ap = g_agg + (size_t)node * 128;
    ap[lane]      = s0 * (1.f / 16.f);
    ap[32 + lane] = s1 * (1.f / 16.f);
    ap[64 + lane] = m0;
    ap[96 + lane] = m1;
}

// ============================================================
// Kernel 3b: W_out [256,128] -> transposed bf16 hi/lo B[n][k].
// ============================================================
__global__ __launch_bounds__(512) void k_wcvt(const float* __restrict__ Wout)
{
    int idx = blockIdx.x * 512 + threadIdx.x;      // 0..32767
    int n = idx & 127, k = idx >> 7;
    float w = Wout[(size_t)k * 128 + n];
    __nv_bfloat16 hb = __float2bfloat16_rn(w);
    g_Bhi[n * 256 + k] = hb;
    g_Blo[n * 256 + k] = __float2bfloat16_rn(w - __bfloat162float(hb));
}

// ============================================================
// Kernel 4: out = relu([x|agg] @ W_out + b_out)
//   HMMA bf16 (mma.sync.m16n8k16) with 3-term split precision:
//   Ahi*Bhi + Ahi*Blo + Alo*Bhi, fp32 register accumulators.
//   CTA: 128x128, K=256 in 8 chunks of 32. 8 warps, 64x32 each.
//   smem pitch 40 bf16 (80B) -> ldmatrix conflict-free.
// ============================================================
#define APITCH 40

__global__ __launch_bounds__(256) void k_out(
    const float* __restrict__ x,
    const float* __restrict__ bout,
    float* __restrict__ out)
{
    __shared__ __nv_bfloat16 Ahi_s[128][APITCH];
    __shared__ __nv_bfloat16 Alo_s[128][APITCH];
    __shared__ __nv_bfloat16 Bhi_s[128][APITCH];
    __shared__ __nv_bfloat16 Blo_s[128][APITCH];

    int t = threadIdx.x;
    int wid = t >> 5, lane = t & 31;
    int warp_m = wid & 1;        // 2 warps over M: 64 rows each
    int warp_n = wid >> 1;       // 4 warps over N: 32 cols each
    int block_row = blockIdx.x * 128;

    float acc[4][4][4];          // [mi][ni][reg]
#pragma unroll
    for (int mi = 0; mi < 4; mi++)
#pragma unroll
        for (int ni = 0; ni < 4; ni++)
#pragma unroll
            for (int r = 0; r < 4; r++) acc[mi][ni][r] = 0.f;

    // per-lane ldmatrix source coordinates (g = lane/8, r = lane%8)
    int lg = lane >> 3, lr = lane & 7;
    int a_row_off = (lg & 1) * 8 + lr;       // + mi*16 + warp_m*64
    int a_col_off = (lg >> 1) * 8;           // + ks*16
    int b_row_off = (lg >> 1) * 8 + lr;      // n within 16-block
    int b_col_off = (lg & 1) * 8;            // k within 16

    uint32_t sbAhi = smem_u32(&Ahi_s[0][0]);
    uint32_t sbAlo = smem_u32(&Alo_s[0][0]);
    uint32_t sbBhi = smem_u32(&Bhi_s[0][0]);
    uint32_t sbBlo = smem_u32(&Blo_s[0][0]);

    for (int kc = 0; kc < 8; kc++) {
        // ---- stage A chunk: 128 rows x 32 k, fp32 -> bf16 hi/lo ----
        const float* srcA = ((kc < 4) ? x : g_agg) + (kc & 3) * 32;
#pragma unroll
        for (int it = 0; it < 4; it++) {
            int task = t + it * 256;          // 0..1023
            int r = task >> 3, q = task & 7;  // row, float4 index
            float4 v = __ldg((const float4*)(srcA + (size_t)(block_row + r) * 128 + q * 4));
            __nv_bfloat16 h0 = __float2bfloat16_rn(v.x);
            __nv_bfloat16 h1 = __float2bfloat16_rn(v.y);
            __nv_bfloat16 h2 = __float2bfloat16_rn(v.z);
            __nv_bfloat16 h3 = __float2bfloat16_rn(v.w);
            __nv_bfloat16 l0 = __float2bfloat16_rn(v.x - __bfloat162float(h0));
            __nv_bfloat16 l1 = __float2bfloat16_rn(v.y - __bfloat162float(h1));
            __nv_bfloat16 l2 = __float2bfloat16_rn(v.z - __bfloat162float(h2));
            __nv_bfloat16 l3 = __float2bfloat16_rn(v.w - __bfloat162float(h3));
            *(uint2*)&Ahi_s[r][q * 4] = make_uint2(pack_bf2(h0, h1), pack_bf2(h2, h3));
            *(uint2*)&Alo_s[r][q * 4] = make_uint2(pack_bf2(l0, l1), pack_bf2(l2, l3));
        }
        // ---- stage B chunk: 128 n x 32 k (already bf16 hi/lo) ----
#pragma unroll
        for (int it = 0; it < 2; it++) {
            int task = t + it * 256;          // 0..511
            int n = task >> 2, q = task & 3;  // row, uint4 index
            uint4 hv = __ldg((const uint4*)(g_Bhi + n * 256 + kc * 32 + q * 8));
            uint4 lv = __ldg((const uint4*)(g_Blo + n * 256 + kc * 32 + q * 8));
            *(uint4*)&Bhi_s[n][q * 8] = hv;
            *(uint4*)&Blo_s[n][q * 8] = lv;
        }
        __syncthreads();

#pragma unroll
        for (int ks = 0; ks < 2; ks++) {
            uint32_t a[4][4], bhi[4][2], blo[4][2];
            // B frags: one x4 covers 2 n-tiles (16 n) for this k16 step
#pragma unroll
            for (int np = 0; np < 2; np++) {
                uint32_t addr = sbBhi +
                    ((warp_n * 32 + np * 16 + b_row_off) * APITCH + ks * 16 + b_col_off) * 2;
                LDSM_X4(bhi[np * 2][0], bhi[np * 2][1],
                        bhi[np * 2 + 1][0], bhi[np * 2 + 1][1], addr);
                addr = sbBlo +
                    ((warp_n * 32 + np * 16 + b_row_off) * APITCH + ks * 16 + b_col_off) * 2;
                LDSM_X4(blo[np * 2][0], blo[np * 2][1],
                        blo[np * 2 + 1][0], blo[np * 2 + 1][1], addr);
            }
            // A hi frags
#pragma unroll
            for (int mi = 0; mi < 4; mi++) {
                uint32_t addr = sbAhi +
                    ((warp_m * 64 + mi * 16 + a_row_off) * APITCH + ks * 16 + a_col_off) * 2;
                LDSM_X4(a[mi][0], a[mi][1], a[mi][2], a[mi][3], addr);
            }
            // pass 1 + 2: Ahi*Bhi, Ahi*Blo
#pragma unroll
            for (int mi = 0; mi < 4; mi++)
#pragma unroll
                for (int ni = 0; ni < 4; ni++) {
                    MMA16816(acc[mi][ni], a[mi], bhi[ni]);
                    MMA16816(acc[mi][ni], a[mi], blo[ni]);
                }
            // A lo frags (reuse regs), pass 3: Alo*Bhi
#pragma unroll
            for (int mi = 0; mi < 4; mi++) {
                uint32_t addr = sbAlo +
                    ((warp_m * 64 + mi * 16 + a_row_off) * APITCH + ks * 16 + a_col_off) * 2;
                LDSM_X4(a[mi][0], a[mi][1], a[mi][2], a[mi][3], addr);
            }
#pragma unroll
            for (int mi = 0; mi < 4; mi++)
#pragma unroll
                for (int ni = 0; ni < 4; ni++)
                    MMA16816(acc[mi][ni], a[mi], bhi[ni]);
        }
        __syncthreads();
    }

    // ---- epilogue: bias + relu, float2 stores ----
    int qrow = lane >> 2, qcol = (lane & 3) * 2;
    float2 bias2[4];
#pragma unroll
    for (int ni = 0; ni < 4; ni++)
        bias2[ni] = *(const float2*)(bout + warp_n * 32 + ni * 8 + qcol);

#pragma unroll
    for (int mi = 0; mi < 4; mi++) {
        int row0 = block_row + warp_m * 64 + mi * 16 + qrow;
#pragma unroll
        for (int ni = 0; ni < 4; ni++) {
            int col = warp_n * 32 + ni * 8 + qcol;
            float2 v0, v1;
            v0.x = fmaxf(acc[mi][ni][0] + bias2[ni].x, 0.f);
            v0.y = fmaxf(acc[mi][ni][1] + bias2[ni].y, 0.f);
            v1.x = fmaxf(acc[mi][ni][2] + bias2[ni].x, 0.f);
            v1.y = fmaxf(acc[mi][ni][3] + bias2[ni].y, 0.f);
            *(float2*)(out + (size_t)row0 * 128 + col)       = v0;
            *(float2*)(out + (size_t)(row0 + 8) * 128 + col) = v1;
        }
    }
}

// ============================================================
extern "C" void kernel_launch(void* const* d_in, const int* in_sizes, int n_in,
                              void* d_out, int out_size)
{
    const float* x    = (const float*)d_in[0];
    const float* Ws   = (const float*)d_in[1];
    const float* bs   = (const float*)d_in[2];
    const float* Wh   = (const float*)d_in[3];
    const float* bh   = (const float*)d_in[4];
    const float* Wout = (const float*)d_in[5];
    const float* bout = (const float*)d_in[6];
    float* out = (float*)d_out;

    k_wcvt<<<64, 512>>>(Wout);
    k_embed<<<Ntot / 32, 256>>>(x, Ws, bs, Wh, bh);
    k_knn<<<dim3(Bg, 2), 512>>>();
    k_agg<<<Ntot / 8, 256>>>();
    k_out<<<Ntot / 128, 256>>>(x, bout, out);
}

// round 8
// speedup vs baseline: 2.1867x; 1.1395x over previous
#include <cuda_runtime.h>
#include <cuda_bf16.h>
#include <cstdint>
#include <float.h>

#define Bg   64
#define Lg   1024
#define Kn   16
#define Ntot (Bg * Lg)

// ---- scratch (static device globals; zero-initialized; no allocation) ----
__device__ float g_s[Ntot * 4];             //  1 MB  learned kNN space
__device__ float g_h[Ntot * 64];            // 16 MB  propagated features (fp32 for agg)
__device__ float g_w[Ntot * Kn];            //  4 MB  edge weights
__device__ int   g_id[Ntot * Kn];           //  4 MB  neighbor indices
__device__ __nv_bfloat16 g_xhi[Ntot * 128]; // 16 MB  x split hi   [node][k]
__device__ __nv_bfloat16 g_xlo[Ntot * 128]; // 16 MB  x split lo
__device__ __nv_bfloat16 g_ahi[Ntot * 128]; // 16 MB  agg split hi [node][mean|max]
__device__ __nv_bfloat16 g_alo[Ntot * 128]; // 16 MB  agg split lo
__device__ __nv_bfloat16 g_Bhi[128 * 256];  // W_out^T hi  [n][k=256]
__device__ __nv_bfloat16 g_Blo[128 * 256];  // W_out^T lo
__device__ __nv_bfloat16 g_Ehi[96 * 128];   // W_comb^T hi [n=96(pad)][k=128]
__device__ __nv_bfloat16 g_Elo[96 * 128];   // W_comb^T lo (rows 72..95 stay zero)

__device__ __forceinline__ uint32_t smem_u32(const void* p) {
    uint32_t a;
    asm("{ .reg .u64 t; cvta.to.shared.u64 t, %1; cvt.u32.u64 %0, t; }"
        : "=r"(a) : "l"(p));
    return a;
}

#define LDSM_X4(r0, r1, r2, r3, addr) \
    asm volatile("ldmatrix.sync.aligned.m8n8.x4.shared.b16 {%0,%1,%2,%3}, [%4];" \
                 : "=r"(r0), "=r"(r1), "=r"(r2), "=r"(r3) : "r"(addr))

#define MMA16816(c, a, b) \
    asm volatile("mma.sync.aligned.m16n8k16.row.col.f32.bf16.bf16.f32 " \
                 "{%0,%1,%2,%3}, {%4,%5,%6,%7}, {%8,%9}, {%0,%1,%2,%3};" \
                 : "+f"((c)[0]), "+f"((c)[1]), "+f"((c)[2]), "+f"((c)[3]) \
                 : "r"((a)[0]), "r"((a)[1]), "r"((a)[2]), "r"((a)[3]), \
                   "r"((b)[0]), "r"((b)[1]))

__device__ __forceinline__ unsigned pack_bf2(__nv_bfloat16 a, __nv_bfloat16 b) {
    __nv_bfloat162 p = __halves2bfloat162(a, b);
    return *reinterpret_cast<unsigned*>(&p);
}
__device__ __forceinline__ void split_bf(float v, __nv_bfloat16& h, __nv_bfloat16& l) {
    h = __float2bfloat16_rn(v);
    l = __float2bfloat16_rn(v - __bfloat162float(h));
}

// ============================================================
// Kernel 0: weight prep.
//   g_Bhi/Blo : W_out^T [128 n][256 k] hi/lo
//   g_Ehi/Elo : combined embed W^T [72 n][128 k] (n<64: W_h, 64..67: W_s)
// ============================================================
__global__ __launch_bounds__(512) void k_wcvt(
    const float* __restrict__ Wout,
    const float* __restrict__ Ws, const float* __restrict__ Wh)
{
    int idx = blockIdx.x * 512 + threadIdx.x;      // 0..32767
    {
        int n = idx & 127, k = idx >> 7;
        float w = Wout[(size_t)k * 128 + n];
        __nv_bfloat16 h, l;
        split_bf(w, h, l);
        g_Bhi[n * 256 + k] = h;
        g_Blo[n * 256 + k] = l;
    }
    if (idx < 72 * 128) {
        int n = idx >> 7, k = idx & 127;
        float w = (n < 64) ? Wh[k * 64 + n] : Ws[k * 4 + (n - 64)];
        __nv_bfloat16 h, l;
        split_bf(w, h, l);
        g_Ehi[n * 128 + k] = h;
        g_Elo[n * 128 + k] = l;
    }
}

// ============================================================
// Kernel 1: fused s/h embedding via HMMA split-bf16.
//   [64 rows/CTA] x [80 n (64 h + 4 s + pad)] , K=128 in 2 chunks.
//   A-stage also writes x hi/lo to global for k_out reuse.
//   8 warps: 4 over M (16 rows), 2 over N (40 cols = 5 tiles).
// ============================================================
#define EP 72   // smem k pitch (64 + 8 pad), rows 144B -> ldsm conflict-free

__global__ __launch_bounds__(256) void k_embed(
    const float* __restrict__ x,
    const float* __restrict__ bs, const float* __restrict__ bh)
{
    __shared__ __nv_bfloat16 Ah[64][EP];
    __shared__ __nv_bfloat16 Al[64][EP];
    __shared__ __nv_bfloat16 Bh[96][EP];
    __shared__ __nv_bfloat16 Bl[96][EP];

    int t = threadIdx.x;
    int wid = t >> 5, lane = t & 31;
    int warp_m = wid & 3;      // 4 x 16 rows
    int warp_n = wid >> 2;     // 2 x 40 cols
    int brow = blockIdx.x * 64;

    float acc[5][4];
#pragma unroll
    for (int ni = 0; ni < 5; ni++)
#pragma unroll
        for (int r = 0; r < 4; r++) acc[ni][r] = 0.f;

    int lg = lane >> 3, lr = lane & 7;
    int a_row_off = (lg & 1) * 8 + lr;
    int a_col_off = (lg >> 1) * 8;
    int b_row_off = (lg >> 1) * 8 + lr;
    int b_col_off = (lg & 1) * 8;

    uint32_t sbAh = smem_u32(&Ah[0][0]);
    uint32_t sbAl = smem_u32(&Al[0][0]);
    uint32_t sbBh = smem_u32(&Bh[0][0]);
    uint32_t sbBl = smem_u32(&Bl[0][0]);

    for (int kc = 0; kc < 2; kc++) {
        // ---- A: convert x[64 x 64] fp32 -> bf16 hi/lo; also write global ----
#pragma unroll
        for (int it = 0; it < 4; it++) {
            int f4 = t + it * 256;            // 0..1023
            int r = f4 >> 4, q = f4 & 15;
            size_t goff = (size_t)(brow + r) * 128 + kc * 64 + q * 4;
            float4 v = __ldg((const float4*)(x + goff));
            __nv_bfloat16 h0, l0, h1, l1, h2, l2, h3, l3;
            split_bf(v.x, h0, l0); split_bf(v.y, h1, l1);
            split_bf(v.z, h2, l2); split_bf(v.w, h3, l3);
            uint2 hv = make_uint2(pack_bf2(h0, h1), pack_bf2(h2, h3));
            uint2 lv = make_uint2(pack_bf2(l0, l1), pack_bf2(l2, l3));
            *(uint2*)&Ah[r][q * 4] = hv;
            *(uint2*)&Al[r][q * 4] = lv;
            *(uint2*)(g_xhi + goff) = hv;
            *(uint2*)(g_xlo + goff) = lv;
        }
        // ---- B: copy E tile rows 0..95, k slice 64 ----
#pragma unroll
        for (int it = 0; it < 3; it++) {
            int task = t + it * 256;          // 0..767
            int n = task >> 3, q = task & 7;
            *(uint4*)&Bh[n][q * 8] = __ldg((const uint4*)(g_Ehi + n * 128 + kc * 64 + q * 8));
            *(uint4*)&Bl[n][q * 8] = __ldg((const uint4*)(g_Elo + n * 128 + kc * 64 + q * 8));
        }
        __syncthreads();

#pragma unroll
        for (int ks = 0; ks < 4; ks++) {
            uint32_t ah[4], al[4], bhi[6][2], blo[6][2];
#pragma unroll
            for (int np = 0; np < 3; np++) {
                uint32_t addr = sbBh +
                    ((warp_n * 40 + np * 16 + b_row_off) * EP + ks * 16 + b_col_off) * 2;
                LDSM_X4(bhi[np * 2][0], bhi[np * 2][1],
                        bhi[np * 2 + 1][0], bhi[np * 2 + 1][1], addr);
                addr = sbBl +
                    ((warp_n * 40 + np * 16 + b_row_off) * EP + ks * 16 + b_col_off) * 2;
                LDSM_X4(blo[np * 2][0], blo[np * 2][1],
                        blo[np * 2 + 1][0], blo[np * 2 + 1][1], addr);
            }
            {
                uint32_t addr = sbAh +
                    ((warp_m * 16 + a_row_off) * EP + ks * 16 + a_col_off) * 2;
                LDSM_X4(ah[0], ah[1], ah[2], ah[3], addr);
                addr = sbAl +
                    ((warp_m * 16 + a_row_off) * EP + ks * 16 + a_col_off) * 2;
                LDSM_X4(al[0], al[1], al[2], al[3], addr);
            }
#pragma unroll
            for (int ni = 0; ni < 5; ni++) {
                MMA16816(acc[ni], ah, bhi[ni]);
                MMA16816(acc[ni], ah, blo[ni]);
                MMA16816(acc[ni], al, bhi[ni]);
            }
        }
        __syncthreads();
    }

    // ---- epilogue: cols <64 -> g_h (+bh), 64..67 -> g_s (+bs) ----
    int qrow = lane >> 2, qcol = (lane & 3) * 2;
    int row0 = brow + warp_m * 16 + qrow;
#pragma unroll
    for (int ni = 0; ni < 5; ni++) {
        int c = warp_n * 40 + ni * 8 + qcol;
        if (c < 64) {
            float2 b2 = *(const float2*)(bh + c);
            float2 v0 = make_float2(acc[ni][0] + b2.x, acc[ni][1] + b2.y);
            float2 v1 = make_float2(acc[ni][2] + b2.x, acc[ni][3] + b2.y);
            *(float2*)(g_h + (size_t)row0 * 64 + c)       = v0;
            *(float2*)(g_h + (size_t)(row0 + 8) * 64 + c) = v1;
        } else if (c < 68) {
            int sc = c - 64;
            float2 b2 = *(const float2*)(bs + sc);
            float2 v0 = make_float2(acc[ni][0] + b2.x, acc[ni][1] + b2.y);
            float2 v1 = make_float2(acc[ni][2] + b2.x, acc[ni][3] + b2.y);
            *(float2*)(g_s + (size_t)row0 * 4 + sc)       = v0;
            *(float2*)(g_s + (size_t)(row0 + 8) * 4 + sc) = v1;
        }
    }
}

// ============================================================
// Kernel 2: per-graph kNN (R3 proven; packed (d2,idx) FMNMX chain).
// ============================================================
__global__ __launch_bounds__(512) void k_knn()
{
    __shared__ float4 sg[Lg];
    int b = blockIdx.x;
    int base = b * Lg;

    const float4* sp = (const float4*)(g_s + (size_t)base * 4);
    for (int i = threadIdx.x; i < Lg; i += blockDim.x) sg[i] = sp[i];
    __syncthreads();

    int i = blockIdx.y * blockDim.x + threadIdx.x;
    float4 si = sg[i];

    float lst[Kn];
#pragma unroll
    for (int tt = 0; tt < Kn; tt++) lst[tt] = FLT_MAX;

#pragma unroll 4
    for (int j = 0; j < Lg; j++) {
        float4 sj = sg[j];
        float dx = si.x - sj.x, dy = si.y - sj.y;
        float dz = si.z - sj.z, dw = si.w - sj.w;
        float d2 = dx * dx + dy * dy;
        d2 = fmaf(dz, dz, d2);
        d2 = fmaf(dw, dw, d2);
        float pv = __uint_as_float((__float_as_uint(d2) & 0xFFFFFC00u) | (unsigned)j);
        if (pv < lst[Kn - 1]) {
            float v = pv;
#pragma unroll
            for (int tt = 0; tt < Kn; tt++) {
                float lo = fminf(v, lst[tt]);
                v       = fmaxf(v, lst[tt]);
                lst[tt] = lo;
            }
        }
    }

    int   oid[Kn];
    float ow [Kn];
#pragma unroll
    for (int tt = 0; tt < Kn; tt++) {
        int j = (int)(__float_as_uint(lst[tt]) & 1023u);
        float4 sj = sg[j];
        float dx = si.x - sj.x, dy = si.y - sj.y;
        float dz = si.z - sj.z, dw = si.w - sj.w;
        float d2 = dx * dx + dy * dy;
        d2 = fmaf(dz, dz, d2);
        d2 = fmaf(dw, dw, d2);
        oid[tt] = base + j;
        ow [tt] = __expf(-10.f * d2);
    }
    int4*   idp = (int4*)  (g_id + (size_t)(base + i) * Kn);
    float4* wp  = (float4*)(g_w  + (size_t)(base + i) * Kn);
#pragma unroll
    for (int q = 0; q < 4; q++) {
        idp[q] = make_int4(oid[q*4], oid[q*4+1], oid[q*4+2], oid[q*4+3]);
        wp [q] = make_float4(ow[q*4], ow[q*4+1], ow[q*4+2], ow[q*4+3]);
    }
}

// ============================================================
// Kernel 3: warp-per-node gather + mean/max; outputs bf16 hi/lo.
// ============================================================
__global__ __launch_bounds__(256) void k_agg()
{
    int node = (blockIdx.x * blockDim.x + threadIdx.x) >> 5;
    int lane = threadIdx.x & 31;
    if (node >= Ntot) return;

    int   myid = 0;
    float mywt = 0.f;
    if (lane < Kn) {
        myid = g_id[(size_t)node * Kn + lane];
        mywt = g_w [(size_t)node * Kn + lane];
    }
    float s0 = 0.f, s1 = 0.f, m0 = -FLT_MAX, m1 = -FLT_MAX;
#pragma unroll
    for (int nb = 0; nb < Kn; nb++) {
        int   id = __shfl_sync(0xffffffffu, myid, nb);
        float wt = __shfl_sync(0xffffffffu, mywt, nb);
        float v0 = __ldg(&g_h[(size_t)id * 64 + lane])      * wt;
        float v1 = __ldg(&g_h[(size_t)id * 64 + 32 + lane]) * wt;
        s0 += v0;  s1 += v1;
        m0 = fmaxf(m0, v0);  m1 = fmaxf(m1, v1);
    }
    size_t bidx = (size_t)node * 128;
    float vals[4] = { s0 * (1.f / 16.f), s1 * (1.f / 16.f), m0, m1 };
    int   cols[4] = { lane, 32 + lane, 64 + lane, 96 + lane };
#pragma unroll
    for (int q = 0; q < 4; q++) {
        __nv_bfloat16 h, l;
        split_bf(vals[q], h, l);
        g_ahi[bidx + cols[q]] = h;
        g_alo[bidx + cols[q]] = l;
    }
}

// ============================================================
// Kernel 4: out = relu([x|agg] @ W_out + b_out)
//   HMMA 3-term split; A/B staged as PRE-SPLIT bf16 copies.
//   CTA 128x128, K=256 in 8 chunks of 32. (R7-proven frag maps)
// ============================================================
#define APITCH 40

__global__ __launch_bounds__(256) void k_out(
    const float* __restrict__ bout,
    float* __restrict__ out)
{
    __shared__ __nv_bfloat16 Ahi_s[128][APITCH];
    __shared__ __nv_bfloat16 Alo_s[128][APITCH];
    __shared__ __nv_bfloat16 Bhi_s[128][APITCH];
    __shared__ __nv_bfloat16 Blo_s[128][APITCH];

    int t = threadIdx.x;
    int wid = t >> 5, lane = t & 31;
    int warp_m = wid & 1;
    int warp_n = wid >> 1;
    int block_row = blockIdx.x * 128;

    float acc[4][4][4];
#pragma unroll
    for (int mi = 0; mi < 4; mi++)
#pragma unroll
        for (int ni = 0; ni < 4; ni++)
#pragma unroll
            for (int r = 0; r < 4; r++) acc[mi][ni][r] = 0.f;

    int lg = lane >> 3, lr = lane & 7;
    int a_row_off = (lg & 1) * 8 + lr;
    int a_col_off = (lg >> 1) * 8;
    int b_row_off = (lg >> 1) * 8 + lr;
    int b_col_off = (lg & 1) * 8;

    uint32_t sbAhi = smem_u32(&Ahi_s[0][0]);
    uint32_t sbAlo = smem_u32(&Alo_s[0][0]);
    uint32_t sbBhi = smem_u32(&Bhi_s[0][0]);
    uint32_t sbBlo = smem_u32(&Blo_s[0][0]);

    for (int kc = 0; kc < 8; kc++) {
        // ---- A: copy pre-split bf16, 128 rows x 32 k ----
        const __nv_bfloat16* sh = ((kc < 4) ? g_xhi : g_ahi) + (kc & 3) * 32;
        const __nv_bfloat16* sl = ((kc < 4) ? g_xlo : g_alo) + (kc & 3) * 32;
#pragma unroll
        for (int it = 0; it < 2; it++) {
            int task = t + it * 256;          // 0..511
            int r = task >> 2, q = task & 3;
            size_t goff = (size_t)(block_row + r) * 128 + q * 8;
            *(uint4*)&Ahi_s[r][q * 8] = __ldg((const uint4*)(sh + goff));
            *(uint4*)&Alo_s[r][q * 8] = __ldg((const uint4*)(sl + goff));
        }
        // ---- B: copy bf16 hi/lo, 128 n x 32 k ----
#pragma unroll
        for (int it = 0; it < 2; it++) {
            int task = t + it * 256;
            int n = task >> 2, q = task & 3;
            *(uint4*)&Bhi_s[n][q * 8] = __ldg((const uint4*)(g_Bhi + n * 256 + kc * 32 + q * 8));
            *(uint4*)&Blo_s[n][q * 8] = __ldg((const uint4*)(g_Blo + n * 256 + kc * 32 + q * 8));
        }
        __syncthreads();

#pragma unroll
        for (int ks = 0; ks < 2; ks++) {
            uint32_t a[4][4], bhi[4][2], blo[4][2];
#pragma unroll
            for (int np = 0; np < 2; np++) {
                uint32_t addr = sbBhi +
                    ((warp_n * 32 + np * 16 + b_row_off) * APITCH + ks * 16 + b_col_off) * 2;
                LDSM_X4(bhi[np * 2][0], bhi[np * 2][1],
                        bhi[np * 2 + 1][0], bhi[np * 2 + 1][1], addr);
                addr = sbBlo +
                    ((warp_n * 32 + np * 16 + b_row_off) * APITCH + ks * 16 + b_col_off) * 2;
                LDSM_X4(blo[np * 2][0], blo[np * 2][1],
                        blo[np * 2 + 1][0], blo[np * 2 + 1][1], addr);
            }
#pragma unroll
            for (int mi = 0; mi < 4; mi++) {
                uint32_t addr = sbAhi +
                    ((warp_m * 64 + mi * 16 + a_row_off) * APITCH + ks * 16 + a_col_off) * 2;
                LDSM_X4(a[mi][0], a[mi][1], a[mi][2], a[mi][3], addr);
            }
#pragma unroll
            for (int mi = 0; mi < 4; mi++)
#pragma unroll
                for (int ni = 0; ni < 4; ni++) {
                    MMA16816(acc[mi][ni], a[mi], bhi[ni]);
                    MMA16816(acc[mi][ni], a[mi], blo[ni]);
                }
#pragma unroll
            for (int mi = 0; mi < 4; mi++) {
                uint32_t addr = sbAlo +
                    ((warp_m * 64 + mi * 16 + a_row_off) * APITCH + ks * 16 + a_col_off) * 2;
                LDSM_X4(a[mi][0], a[mi][1], a[mi][2], a[mi][3], addr);
            }
#pragma unroll
            for (int mi = 0; mi < 4; mi++)
#pragma unroll
                for (int ni = 0; ni < 4; ni++)
                    MMA16816(acc[mi][ni], a[mi], bhi[ni]);
        }
        __syncthreads();
    }

    int qrow = lane >> 2, qcol = (lane & 3) * 2;
    float2 bias2[4];
#pragma unroll
    for (int ni = 0; ni < 4; ni++)
        bias2[ni] = *(const float2*)(bout + warp_n * 32 + ni * 8 + qcol);

#pragma unroll
    for (int mi = 0; mi < 4; mi++) {
        int row0 = block_row + warp_m * 64 + mi * 16 + qrow;
#pragma unroll
        for (int ni = 0; ni < 4; ni++) {
            int col = warp_n * 32 + ni * 8 + qcol;
            float2 v0, v1;
            v0.x = fmaxf(acc[mi][ni][0] + bias2[ni].x, 0.f);
            v0.y = fmaxf(acc[mi][ni][1] + bias2[ni].y, 0.f);
            v1.x = fmaxf(acc[mi][ni][2] + bias2[ni].x, 0.f);
            v1.y = fmaxf(acc[mi][ni][3] + bias2[ni].y, 0.f);
            *(float2*)(out + (size_t)row0 * 128 + col)       = v0;
            *(float2*)(out + (size_t)(row0 + 8) * 128 + col) = v1;
        }
    }
}

// ============================================================
extern "C" void kernel_launch(void* const* d_in, const int* in_sizes, int n_in,
                              void* d_out, int out_size)
{
    const float* x    = (const float*)d_in[0];
    const float* Ws   = (const float*)d_in[1];
    const float* bs   = (const float*)d_in[2];
    const float* Wh   = (const float*)d_in[3];
    const float* bh   = (const float*)d_in[4];
    const float* Wout = (const float*)d_in[5];
    const float* bout = (const float*)d_in[6];
    float* out = (float*)d_out;

    k_wcvt<<<64, 512>>>(Wout, Ws, Wh);
    k_embed<<<Ntot / 64, 256>>>(x, bs, bh);
    k_knn<<<dim3(Bg, 2), 512>>>();
    k_agg<<<Ntot / 8, 256>>>();
    k_out<<<Ntot / 128, 256>>>(bout, out);
}

// round 9
// speedup vs baseline: 2.5534x; 1.1677x over previous
#include <cuda_runtime.h>
#include <cuda_bf16.h>
#include <cstdint>
#include <float.h>

#define Bg   64
#define Lg   1024
#define Kn   16
#define Ntot (Bg * Lg)

// ---- scratch (static device globals; zero-initialized; no allocation) ----
__device__ float g_s[Ntot * 4];             //  1 MB  learned kNN space
__device__ float g_h[Ntot * 64];            // 16 MB  propagated features (fp32 for agg)
__device__ float g_w[Ntot * Kn];            //  4 MB  edge weights
__device__ int   g_id[Ntot * Kn];           //  4 MB  neighbor indices
__device__ __nv_bfloat16 g_xhi[Ntot * 128]; // 16 MB  x split hi   [node][k]
__device__ __nv_bfloat16 g_xlo[Ntot * 128]; // 16 MB  x split lo
__device__ __nv_bfloat16 g_ahi[Ntot * 128]; // 16 MB  agg split hi [node][mean|max]
__device__ __nv_bfloat16 g_alo[Ntot * 128]; // 16 MB  agg split lo
__device__ __nv_bfloat16 g_Bhi[128 * 256];  // W_out^T hi  [n][k=256]
__device__ __nv_bfloat16 g_Blo[128 * 256];  // W_out^T lo
__device__ __nv_bfloat16 g_Ehi[96 * 128];   // W_comb^T hi [n=96(pad)][k=128]
__device__ __nv_bfloat16 g_Elo[96 * 128];   // W_comb^T lo (rows 72..95 stay zero)

__device__ __forceinline__ uint32_t smem_u32(const void* p) {
    uint32_t a;
    asm("{ .reg .u64 t; cvta.to.shared.u64 t, %1; cvt.u32.u64 %0, t; }"
        : "=r"(a) : "l"(p));
    return a;
}

#define LDSM_X4(r0, r1, r2, r3, addr) \
    asm volatile("ldmatrix.sync.aligned.m8n8.x4.shared.b16 {%0,%1,%2,%3}, [%4];" \
                 : "=r"(r0), "=r"(r1), "=r"(r2), "=r"(r3) : "r"(addr))

#define MMA16816(c, a, b) \
    asm volatile("mma.sync.aligned.m16n8k16.row.col.f32.bf16.bf16.f32 " \
                 "{%0,%1,%2,%3}, {%4,%5,%6,%7}, {%8,%9}, {%0,%1,%2,%3};" \
                 : "+f"((c)[0]), "+f"((c)[1]), "+f"((c)[2]), "+f"((c)[3]) \
                 : "r"((a)[0]), "r"((a)[1]), "r"((a)[2]), "r"((a)[3]), \
                   "r"((b)[0]), "r"((b)[1]))

__device__ __forceinline__ unsigned pack_bf2(__nv_bfloat16 a, __nv_bfloat16 b) {
    __nv_bfloat162 p = __halves2bfloat162(a, b);
    return *reinterpret_cast<unsigned*>(&p);
}
__device__ __forceinline__ void split_bf(float v, __nv_bfloat16& h, __nv_bfloat16& l) {
    h = __float2bfloat16_rn(v);
    l = __float2bfloat16_rn(v - __bfloat162float(h));
}

// ============================================================
// Kernel 0: weight prep (R8 proven).
// ============================================================
__global__ __launch_bounds__(512) void k_wcvt(
    const float* __restrict__ Wout,
    const float* __restrict__ Ws, const float* __restrict__ Wh)
{
    int idx = blockIdx.x * 512 + threadIdx.x;      // 0..32767
    {
        int n = idx & 127, k = idx >> 7;
        float w = Wout[(size_t)k * 128 + n];
        __nv_bfloat16 h, l;
        split_bf(w, h, l);
        g_Bhi[n * 256 + k] = h;
        g_Blo[n * 256 + k] = l;
    }
    if (idx < 72 * 128) {
        int n = idx >> 7, k = idx & 127;
        float w = (n < 64) ? Wh[k * 64 + n] : Ws[k * 4 + (n - 64)];
        __nv_bfloat16 h, l;
        split_bf(w, h, l);
        g_Ehi[n * 128 + k] = h;
        g_Elo[n * 128 + k] = l;
    }
}

// ============================================================
// Kernel 1: fused s/h embedding via HMMA split-bf16 (R8 proven).
// ============================================================
#define EP 72

__global__ __launch_bounds__(256) void k_embed(
    const float* __restrict__ x,
    const float* __restrict__ bs, const float* __restrict__ bh)
{
    __shared__ __nv_bfloat16 Ah[64][EP];
    __shared__ __nv_bfloat16 Al[64][EP];
    __shared__ __nv_bfloat16 Bh[96][EP];
    __shared__ __nv_bfloat16 Bl[96][EP];

    int t = threadIdx.x;
    int wid = t >> 5, lane = t & 31;
    int warp_m = wid & 3;
    int warp_n = wid >> 2;
    int brow = blockIdx.x * 64;

    float acc[5][4];
#pragma unroll
    for (int ni = 0; ni < 5; ni++)
#pragma unroll
        for (int r = 0; r < 4; r++) acc[ni][r] = 0.f;

    int lg = lane >> 3, lr = lane & 7;
    int a_row_off = (lg & 1) * 8 + lr;
    int a_col_off = (lg >> 1) * 8;
    int b_row_off = (lg >> 1) * 8 + lr;
    int b_col_off = (lg & 1) * 8;

    uint32_t sbAh = smem_u32(&Ah[0][0]);
    uint32_t sbAl = smem_u32(&Al[0][0]);
    uint32_t sbBh = smem_u32(&Bh[0][0]);
    uint32_t sbBl = smem_u32(&Bl[0][0]);

    for (int kc = 0; kc < 2; kc++) {
#pragma unroll
        for (int it = 0; it < 4; it++) {
            int f4 = t + it * 256;
            int r = f4 >> 4, q = f4 & 15;
            size_t goff = (size_t)(brow + r) * 128 + kc * 64 + q * 4;
            float4 v = __ldg((const float4*)(x + goff));
            __nv_bfloat16 h0, l0, h1, l1, h2, l2, h3, l3;
            split_bf(v.x, h0, l0); split_bf(v.y, h1, l1);
            split_bf(v.z, h2, l2); split_bf(v.w, h3, l3);
            uint2 hv = make_uint2(pack_bf2(h0, h1), pack_bf2(h2, h3));
            uint2 lv = make_uint2(pack_bf2(l0, l1), pack_bf2(l2, l3));
            *(uint2*)&Ah[r][q * 4] = hv;
            *(uint2*)&Al[r][q * 4] = lv;
            *(uint2*)(g_xhi + goff) = hv;
            *(uint2*)(g_xlo + goff) = lv;
        }
#pragma unroll
        for (int it = 0; it < 3; it++) {
            int task = t + it * 256;
            int n = task >> 3, q = task & 7;
            *(uint4*)&Bh[n][q * 8] = __ldg((const uint4*)(g_Ehi + n * 128 + kc * 64 + q * 8));
            *(uint4*)&Bl[n][q * 8] = __ldg((const uint4*)(g_Elo + n * 128 + kc * 64 + q * 8));
        }
        __syncthreads();

#pragma unroll
        for (int ks = 0; ks < 4; ks++) {
            uint32_t ah[4], al[4], bhi[6][2], blo[6][2];
#pragma unroll
            for (int np = 0; np < 3; np++) {
                uint32_t addr = sbBh +
                    ((warp_n * 40 + np * 16 + b_row_off) * EP + ks * 16 + b_col_off) * 2;
                LDSM_X4(bhi[np * 2][0], bhi[np * 2][1],
                        bhi[np * 2 + 1][0], bhi[np * 2 + 1][1], addr);
                addr = sbBl +
                    ((warp_n * 40 + np * 16 + b_row_off) * EP + ks * 16 + b_col_off) * 2;
                LDSM_X4(blo[np * 2][0], blo[np * 2][1],
                        blo[np * 2 + 1][0], blo[np * 2 + 1][1], addr);
            }
            {
                uint32_t addr = sbAh +
                    ((warp_m * 16 + a_row_off) * EP + ks * 16 + a_col_off) * 2;
                LDSM_X4(ah[0], ah[1], ah[2], ah[3], addr);
                addr = sbAl +
                    ((warp_m * 16 + a_row_off) * EP + ks * 16 + a_col_off) * 2;
                LDSM_X4(al[0], al[1], al[2], al[3], addr);
            }
#pragma unroll
            for (int ni = 0; ni < 5; ni++) {
                MMA16816(acc[ni], ah, bhi[ni]);
                MMA16816(acc[ni], ah, blo[ni]);
                MMA16816(acc[ni], al, bhi[ni]);
            }
        }
        __syncthreads();
    }

    int qrow = lane >> 2, qcol = (lane & 3) * 2;
    int row0 = brow + warp_m * 16 + qrow;
#pragma unroll
    for (int ni = 0; ni < 5; ni++) {
        int c = warp_n * 40 + ni * 8 + qcol;
        if (c < 64) {
            float2 b2 = *(const float2*)(bh + c);
            float2 v0 = make_float2(acc[ni][0] + b2.x, acc[ni][1] + b2.y);
            float2 v1 = make_float2(acc[ni][2] + b2.x, acc[ni][3] + b2.y);
            *(float2*)(g_h + (size_t)row0 * 64 + c)       = v0;
            *(float2*)(g_h + (size_t)(row0 + 8) * 64 + c) = v1;
        } else if (c < 68) {
            int sc = c - 64;
            float2 b2 = *(const float2*)(bs + sc);
            float2 v0 = make_float2(acc[ni][0] + b2.x, acc[ni][1] + b2.y);
            float2 v1 = make_float2(acc[ni][2] + b2.x, acc[ni][3] + b2.y);
            *(float2*)(g_s + (size_t)row0 * 4 + sc)       = v0;
            *(float2*)(g_s + (size_t)(row0 + 8) * 4 + sc) = v1;
        }
    }
}

// ============================================================
// Kernel 2: per-graph kNN with buffered candidate insertion.
//   Ranking value t(j) = |s_j|^2 - 2 s_i.s_j  (drop +|s_i|^2:
//   constant per row, order-invariant). Hits go into a 4-deep
//   shift-register buffer against a stale (over-accepting) gate;
//   warp flushes together when any lane fills -> insertion chain
//   runs converged instead of per-j divergent.
//   Exact d2 = max(n_i + t, 0) recomputed for the 16 winners.
// ============================================================
#define KNN_CHAIN(v) do { \
    float _v = (v); \
    _Pragma("unroll") \
    for (int _tt = 0; _tt < Kn; _tt++) { \
        float _lo = fminf(_v, lst[_tt]); \
        _v = fmaxf(_v, lst[_tt]); \
        lst[_tt] = _lo; \
    } } while (0)

#define KNN_FLUSH() do { \
    _Pragma("unroll") \
    for (int _k = 0; _k < 4; _k++) { \
        float _bv = (_k == 0) ? b0 : (_k == 1) ? b1 : (_k == 2) ? b2 : b3; \
        if (_k < cnt && _bv < lst[Kn - 1]) KNN_CHAIN(_bv); \
    } \
    cnt = 0; gate = lst[Kn - 1]; } while (0)

__global__ __launch_bounds__(512) void k_knn()
{
    __shared__ float4 sm2[Lg];   // -2 * s_j
    __shared__ float  snj[Lg];   // |s_j|^2
    int b = blockIdx.x;
    int base = b * Lg;

    for (int i = threadIdx.x; i < Lg; i += blockDim.x) {
        float4 s = *(const float4*)(g_s + (size_t)(base + i) * 4);
        sm2[i] = make_float4(-2.f * s.x, -2.f * s.y, -2.f * s.z, -2.f * s.w);
        snj[i] = s.x * s.x + s.y * s.y + s.z * s.z + s.w * s.w;
    }
    __syncthreads();

    int i = blockIdx.y * blockDim.x + threadIdx.x;
    float4 m2i = sm2[i];
    float4 si = make_float4(-0.5f * m2i.x, -0.5f * m2i.y, -0.5f * m2i.z, -0.5f * m2i.w);
    float ni = snj[i];

    float lst[Kn];
#pragma unroll
    for (int tt = 0; tt < Kn; tt++) lst[tt] = FLT_MAX;

    float b0 = 0.f, b1 = 0.f, b2 = 0.f, b3 = 0.f;
    int cnt = 0;
    float gate = FLT_MAX;

#pragma unroll 4
    for (int j = 0; j < Lg; j++) {
        float4 mj = sm2[j];
        float tv = fmaf(mj.x, si.x, snj[j]);
        tv = fmaf(mj.y, si.y, tv);
        tv = fmaf(mj.z, si.z, tv);
        tv = fmaf(mj.w, si.w, tv);
        float pv = __uint_as_float((__float_as_uint(tv) & 0xFFFFFC00u) | (unsigned)j);
        if (pv < gate) {              // stale gate: over-accepts, never misses
            b3 = b2; b2 = b1; b1 = b0; b0 = pv;
            cnt++;
        }
        if (__any_sync(0xffffffffu, cnt >= 4)) KNN_FLUSH();
    }
    KNN_FLUSH();                      // drain remaining candidates

    // recover winners: exact d2 (expansion form, matches reference) -> weights
    int   oid[Kn];
    float ow [Kn];
#pragma unroll
    for (int tt = 0; tt < Kn; tt++) {
        int j = (int)(__float_as_uint(lst[tt]) & 1023u);
        float4 mj = sm2[j];
        float tv = fmaf(mj.x, si.x, snj[j]);
        tv = fmaf(mj.y, si.y, tv);
        tv = fmaf(mj.z, si.z, tv);
        tv = fmaf(mj.w, si.w, tv);
        float d2 = fmaxf(ni + tv, 0.f);
        oid[tt] = base + j;
        ow [tt] = __expf(-10.f * d2);
    }
    int4*   idp = (int4*)  (g_id + (size_t)(base + i) * Kn);
    float4* wp  = (float4*)(g_w  + (size_t)(base + i) * Kn);
#pragma unroll
    for (int q = 0; q < 4; q++) {
        idp[q] = make_int4(oid[q*4], oid[q*4+1], oid[q*4+2], oid[q*4+3]);
        wp [q] = make_float4(ow[q*4], ow[q*4+1], ow[q*4+2], ow[q*4+3]);
    }
}

// ============================================================
// Kernel 3: warp-per-node gather + mean/max; bf16 hi/lo out (R8).
// ============================================================
__global__ __launch_bounds__(256) void k_agg()
{
    int node = (blockIdx.x * blockDim.x + threadIdx.x) >> 5;
    int lane = threadIdx.x & 31;
    if (node >= Ntot) return;

    int   myid = 0;
    float mywt = 0.f;
    if (lane < Kn) {
        myid = g_id[(size_t)node * Kn + lane];
        mywt = g_w [(size_t)node * Kn + lane];
    }
    float s0 = 0.f, s1 = 0.f, m0 = -FLT_MAX, m1 = -FLT_MAX;
#pragma unroll
    for (int nb = 0; nb < Kn; nb++) {
        int   id = __shfl_sync(0xffffffffu, myid, nb);
        float wt = __shfl_sync(0xffffffffu, mywt, nb);
        float v0 = __ldg(&g_h[(size_t)id * 64 + lane])      * wt;
        float v1 = __ldg(&g_h[(size_t)id * 64 + 32 + lane]) * wt;
        s0 += v0;  s1 += v1;
        m0 = fmaxf(m0, v0);  m1 = fmaxf(m1, v1);
    }
    size_t bidx = (size_t)node * 128;
    float vals[4] = { s0 * (1.f / 16.f), s1 * (1.f / 16.f), m0, m1 };
    int   cols[4] = { lane, 32 + lane, 64 + lane, 96 + lane };
#pragma unroll
    for (int q = 0; q < 4; q++) {
        __nv_bfloat16 h, l;
        split_bf(vals[q], h, l);
        g_ahi[bidx + cols[q]] = h;
        g_alo[bidx + cols[q]] = l;
    }
}

// ============================================================
// Kernel 4: out = relu([x|agg] @ W_out + b_out)  (R8 proven).
// ============================================================
#define APITCH 40

__global__ __launch_bounds__(256) void k_out(
    const float* __restrict__ bout,
    float* __restrict__ out)
{
    __shared__ __nv_bfloat16 Ahi_s[128][APITCH];
    __shared__ __nv_bfloat16 Alo_s[128][APITCH];
    __shared__ __nv_bfloat16 Bhi_s[128][APITCH];
    __shared__ __nv_bfloat16 Blo_s[128][APITCH];

    int t = threadIdx.x;
    int wid = t >> 5, lane = t & 31;
    int warp_m = wid & 1;
    int warp_n = wid >> 1;
    int block_row = blockIdx.x * 128;

    float acc[4][4][4];
#pragma unroll
    for (int mi = 0; mi < 4; mi++)
#pragma unroll
        for (int ni = 0; ni < 4; ni++)
#pragma unroll
            for (int r = 0; r < 4; r++) acc[mi][ni][r] = 0.f;

    int lg = lane >> 3, lr = lane & 7;
    int a_row_off = (lg & 1) * 8 + lr;
    int a_col_off = (lg >> 1) * 8;
    int b_row_off = (lg >> 1) * 8 + lr;
    int b_col_off = (lg & 1) * 8;

    uint32_t sbAhi = smem_u32(&Ahi_s[0][0]);
    uint32_t sbAlo = smem_u32(&Alo_s[0][0]);
    uint32_t sbBhi = smem_u32(&Bhi_s[0][0]);
    uint32_t sbBlo = smem_u32(&Blo_s[0][0]);

    for (int kc = 0; kc < 8; kc++) {
        const __nv_bfloat16* sh = ((kc < 4) ? g_xhi : g_ahi) + (kc & 3) * 32;
        const __nv_bfloat16* sl = ((kc < 4) ? g_xlo : g_alo) + (kc & 3) * 32;
#pragma unroll
        for (int it = 0; it < 2; it++) {
            int task = t + it * 256;
            int r = task >> 2, q = task & 3;
            size_t goff = (size_t)(block_row + r) * 128 + q * 8;
            *(uint4*)&Ahi_s[r][q * 8] = __ldg((const uint4*)(sh + goff));
            *(uint4*)&Alo_s[r][q * 8] = __ldg((const uint4*)(sl + goff));
        }
#pragma unroll
        for (int it = 0; it < 2; it++) {
            int task = t + it * 256;
            int n = task >> 2, q = task & 3;
            *(uint4*)&Bhi_s[n][q * 8] = __ldg((const uint4*)(g_Bhi + n * 256 + kc * 32 + q * 8));
            *(uint4*)&Blo_s[n][q * 8] = __ldg((const uint4*)(g_Blo + n * 256 + kc * 32 + q * 8));
        }
        __syncthreads();

#pragma unroll
        for (int ks = 0; ks < 2; ks++) {
            uint32_t a[4][4], bhi[4][2], blo[4][2];
#pragma unroll
            for (int np = 0; np < 2; np++) {
                uint32_t addr = sbBhi +
                    ((warp_n * 32 + np * 16 + b_row_off) * APITCH + ks * 16 + b_col_off) * 2;
                LDSM_X4(bhi[np * 2][0], bhi[np * 2][1],
                        bhi[np * 2 + 1][0], bhi[np * 2 + 1][1], addr);
                addr = sbBlo +
                    ((warp_n * 32 + np * 16 + b_row_off) * APITCH + ks * 16 + b_col_off) * 2;
                LDSM_X4(blo[np * 2][0], blo[np * 2][1],
                        blo[np * 2 + 1][0], blo[np * 2 + 1][1], addr);
            }
#pragma unroll
            for (int mi = 0; mi < 4; mi++) {
                uint32_t addr = sbAhi +
                    ((warp_m * 64 + mi * 16 + a_row_off) * APITCH + ks * 16 + a_col_off) * 2;
                LDSM_X4(a[mi][0], a[mi][1], a[mi][2], a[mi][3], addr);
            }
#pragma unroll
            for (int mi = 0; mi < 4; mi++)
#pragma unroll
                for (int ni = 0; ni < 4; ni++) {
                    MMA16816(acc[mi][ni], a[mi], bhi[ni]);
                    MMA16816(acc[mi][ni], a[mi], blo[ni]);
                }
#pragma unroll
            for (int mi = 0; mi < 4; mi++) {
                uint32_t addr = sbAlo +
                    ((warp_m * 64 + mi * 16 + a_row_off) * APITCH + ks * 16 + a_col_off) * 2;
                LDSM_X4(a[mi][0], a[mi][1], a[mi][2], a[mi][3], addr);
            }
#pragma unroll
            for (int mi = 0; mi < 4; mi++)
#pragma unroll
                for (int ni = 0; ni < 4; ni++)
                    MMA16816(acc[mi][ni], a[mi], bhi[ni]);
        }
        __syncthreads();
    }

    int qrow = lane >> 2, qcol = (lane & 3) * 2;
    float2 bias2[4];
#pragma unroll
    for (int ni = 0; ni < 4; ni++)
        bias2[ni] = *(const float2*)(bout + warp_n * 32 + ni * 8 + qcol);

#pragma unroll
    for (int mi = 0; mi < 4; mi++) {
        int row0 = block_row + warp_m * 64 + mi * 16 + qrow;
#pragma unroll
        for (int ni = 0; ni < 4; ni++) {
            int col = warp_n * 32 + ni * 8 + qcol;
            float2 v0, v1;
            v0.x = fmaxf(acc[mi][ni][0] + bias2[ni].x, 0.f);
            v0.y = fmaxf(acc[mi][ni][1] + bias2[ni].y, 0.f);
            v1.x = fmaxf(acc[mi][ni][2] + bias2[ni].x, 0.f);
            v1.y = fmaxf(acc[mi][ni][3] + bias2[ni].y, 0.f);
            *(float2*)(out + (size_t)row0 * 128 + col)       = v0;
            *(float2*)(out + (size_t)(row0 + 8) * 128 + col) = v1;
        }
    }
}

// ============================================================
extern "C" void kernel_launch(void* const* d_in, const int* in_sizes, int n_in,
                              void* d_out, int out_size)
{
    const float* x    = (const float*)d_in[0];
    const float* Ws   = (const float*)d_in[1];
    const float* bs   = (const float*)d_in[2];
    const float* Wh   = (const float*)d_in[3];
    const float* bh   = (const float*)d_in[4];
    const float* Wout = (const float*)d_in[5];
    const float* bout = (const float*)d_in[6];
    float* out = (float*)d_out;

    k_wcvt<<<64, 512>>>(Wout, Ws, Wh);
    k_embed<<<Ntot / 64, 256>>>(x, bs, bh);
    k_knn<<<dim3(Bg, 2), 512>>>();
    k_agg<<<Ntot / 8, 256>>>();
    k_out<<<Ntot / 128, 256>>>(bout, out);
}

// round 10
// speedup vs baseline: 2.5554x; 1.0008x over previous
#include <cuda_runtime.h>
#include <cuda_bf16.h>
#include <cstdint>
#include <float.h>

#define Bg   64
#define Lg   1024
#define Kn   16
#define Ntot (Bg * Lg)

// ---- scratch (static device globals; zero-initialized; no allocation) ----
__device__ float g_s[Ntot * 4];             //  1 MB  learned kNN space
__device__ float g_h[Ntot * 64];            // 16 MB  propagated features (fp32)
__device__ __nv_bfloat16 g_xhi[Ntot * 128]; // 16 MB  x split hi   [node][k]
__device__ __nv_bfloat16 g_xlo[Ntot * 128]; // 16 MB  x split lo
__device__ __nv_bfloat16 g_ahi[Ntot * 128]; // 16 MB  agg split hi [node][mean|max]
__device__ __nv_bfloat16 g_alo[Ntot * 128]; // 16 MB  agg split lo
__device__ __nv_bfloat16 g_Bhi[128 * 256];  // W_out^T hi  [n][k=256]
__device__ __nv_bfloat16 g_Blo[128 * 256];  // W_out^T lo
__device__ __nv_bfloat16 g_Ehi[96 * 128];   // W_comb^T hi [n=96(pad)][k=128]
__device__ __nv_bfloat16 g_Elo[96 * 128];   // W_comb^T lo (rows 72..95 stay zero)

__device__ __forceinline__ uint32_t smem_u32(const void* p) {
    uint32_t a;
    asm("{ .reg .u64 t; cvta.to.shared.u64 t, %1; cvt.u32.u64 %0, t; }"
        : "=r"(a) : "l"(p));
    return a;
}

#define LDSM_X4(r0, r1, r2, r3, addr) \
    asm volatile("ldmatrix.sync.aligned.m8n8.x4.shared.b16 {%0,%1,%2,%3}, [%4];" \
                 : "=r"(r0), "=r"(r1), "=r"(r2), "=r"(r3) : "r"(addr))

#define MMA16816(c, a, b) \
    asm volatile("mma.sync.aligned.m16n8k16.row.col.f32.bf16.bf16.f32 " \
                 "{%0,%1,%2,%3}, {%4,%5,%6,%7}, {%8,%9}, {%0,%1,%2,%3};" \
                 : "+f"((c)[0]), "+f"((c)[1]), "+f"((c)[2]), "+f"((c)[3]) \
                 : "r"((a)[0]), "r"((a)[1]), "r"((a)[2]), "r"((a)[3]), \
                   "r"((b)[0]), "r"((b)[1]))

__device__ __forceinline__ unsigned pack_bf2(__nv_bfloat16 a, __nv_bfloat16 b) {
    __nv_bfloat162 p = __halves2bfloat162(a, b);
    return *reinterpret_cast<unsigned*>(&p);
}
__device__ __forceinline__ void split_bf(float v, __nv_bfloat16& h, __nv_bfloat16& l) {
    h = __float2bfloat16_rn(v);
    l = __float2bfloat16_rn(v - __bfloat162float(h));
}

// ============================================================
// Kernel 0: weight prep (R8 proven).
// ============================================================
__global__ __launch_bounds__(512) void k_wcvt(
    const float* __restrict__ Wout,
    const float* __restrict__ Ws, const float* __restrict__ Wh)
{
    int idx = blockIdx.x * 512 + threadIdx.x;      // 0..32767
    {
        int n = idx & 127, k = idx >> 7;
        float w = Wout[(size_t)k * 128 + n];
        __nv_bfloat16 h, l;
        split_bf(w, h, l);
        g_Bhi[n * 256 + k] = h;
        g_Blo[n * 256 + k] = l;
    }
    if (idx < 72 * 128) {
        int n = idx >> 7, k = idx & 127;
        float w = (n < 64) ? Wh[k * 64 + n] : Ws[k * 4 + (n - 64)];
        __nv_bfloat16 h, l;
        split_bf(w, h, l);
        g_Ehi[n * 128 + k] = h;
        g_Elo[n * 128 + k] = l;
    }
}

// ============================================================
// Kernel 1: fused s/h embedding via HMMA split-bf16 (R8 core,
//   x-split staging now 8-k per thread -> uint4 global stores).
// ============================================================
#define EP 72

__global__ __launch_bounds__(256) void k_embed(
    const float* __restrict__ x,
    const float* __restrict__ bs, const float* __restrict__ bh)
{
    __shared__ __nv_bfloat16 Ah[64][EP];
    __shared__ __nv_bfloat16 Al[64][EP];
    __shared__ __nv_bfloat16 Bh[96][EP];
    __shared__ __nv_bfloat16 Bl[96][EP];

    int t = threadIdx.x;
    int wid = t >> 5, lane = t & 31;
    int warp_m = wid & 3;
    int warp_n = wid >> 2;
    int brow = blockIdx.x * 64;

    float acc[5][4];
#pragma unroll
    for (int ni = 0; ni < 5; ni++)
#pragma unroll
        for (int r = 0; r < 4; r++) acc[ni][r] = 0.f;

    int lg = lane >> 3, lr = lane & 7;
    int a_row_off = (lg & 1) * 8 + lr;
    int a_col_off = (lg >> 1) * 8;
    int b_row_off = (lg >> 1) * 8 + lr;
    int b_col_off = (lg & 1) * 8;

    uint32_t sbAh = smem_u32(&Ah[0][0]);
    uint32_t sbAl = smem_u32(&Al[0][0]);
    uint32_t sbBh = smem_u32(&Bh[0][0]);
    uint32_t sbBl = smem_u32(&Bl[0][0]);

    for (int kc = 0; kc < 2; kc++) {
        // A: 512 tasks of 8 consecutive k -> one uint4 hi + one uint4 lo
#pragma unroll
        for (int it = 0; it < 2; it++) {
            int task = t + it * 256;          // 0..511
            int r = task >> 3, q = task & 7;  // row, 8-k chunk
            size_t goff = (size_t)(brow + r) * 128 + kc * 64 + q * 8;
            float4 v0 = __ldg((const float4*)(x + goff));
            float4 v1 = __ldg((const float4*)(x + goff + 4));
            __nv_bfloat16 h[8], l[8];
            split_bf(v0.x, h[0], l[0]); split_bf(v0.y, h[1], l[1]);
            split_bf(v0.z, h[2], l[2]); split_bf(v0.w, h[3], l[3]);
            split_bf(v1.x, h[4], l[4]); split_bf(v1.y, h[5], l[5]);
            split_bf(v1.z, h[6], l[6]); split_bf(v1.w, h[7], l[7]);
            uint4 hv = make_uint4(pack_bf2(h[0], h[1]), pack_bf2(h[2], h[3]),
                                  pack_bf2(h[4], h[5]), pack_bf2(h[6], h[7]));
            uint4 lv = make_uint4(pack_bf2(l[0], l[1]), pack_bf2(l[2], l[3]),
                                  pack_bf2(l[4], l[5]), pack_bf2(l[6], l[7]));
            *(uint4*)&Ah[r][q * 8] = hv;
            *(uint4*)&Al[r][q * 8] = lv;
            *(uint4*)(g_xhi + goff) = hv;
            *(uint4*)(g_xlo + goff) = lv;
        }
#pragma unroll
        for (int it = 0; it < 3; it++) {
            int task = t + it * 256;
            int n = task >> 3, q = task & 7;
            *(uint4*)&Bh[n][q * 8] = __ldg((const uint4*)(g_Ehi + n * 128 + kc * 64 + q * 8));
            *(uint4*)&Bl[n][q * 8] = __ldg((const uint4*)(g_Elo + n * 128 + kc * 64 + q * 8));
        }
        __syncthreads();

#pragma unroll
        for (int ks = 0; ks < 4; ks++) {
            uint32_t ah[4], al[4], bhi[6][2], blo[6][2];
#pragma unroll
            for (int np = 0; np < 3; np++) {
                uint32_t addr = sbBh +
                    ((warp_n * 40 + np * 16 + b_row_off) * EP + ks * 16 + b_col_off) * 2;
                LDSM_X4(bhi[np * 2][0], bhi[np * 2][1],
                        bhi[np * 2 + 1][0], bhi[np * 2 + 1][1], addr);
                addr = sbBl +
                    ((warp_n * 40 + np * 16 + b_row_off) * EP + ks * 16 + b_col_off) * 2;
                LDSM_X4(blo[np * 2][0], blo[np * 2][1],
                        blo[np * 2 + 1][0], blo[np * 2 + 1][1], addr);
            }
            {
                uint32_t addr = sbAh +
                    ((warp_m * 16 + a_row_off) * EP + ks * 16 + a_col_off) * 2;
                LDSM_X4(ah[0], ah[1], ah[2], ah[3], addr);
                addr = sbAl +
                    ((warp_m * 16 + a_row_off) * EP + ks * 16 + a_col_off) * 2;
                LDSM_X4(al[0], al[1], al[2], al[3], addr);
            }
#pragma unroll
            for (int ni = 0; ni < 5; ni++) {
                MMA16816(acc[ni], ah, bhi[ni]);
                MMA16816(acc[ni], ah, blo[ni]);
                MMA16816(acc[ni], al, bhi[ni]);
            }
        }
        __syncthreads();
    }

    int qrow = lane >> 2, qcol = (lane & 3) * 2;
    int row0 = brow + warp_m * 16 + qrow;
#pragma unroll
    for (int ni = 0; ni < 5; ni++) {
        int c = warp_n * 40 + ni * 8 + qcol;
        if (c < 64) {
            float2 b2 = *(const float2*)(bh + c);
            float2 v0 = make_float2(acc[ni][0] + b2.x, acc[ni][1] + b2.y);
            float2 v1 = make_float2(acc[ni][2] + b2.x, acc[ni][3] + b2.y);
            *(float2*)(g_h + (size_t)row0 * 64 + c)       = v0;
            *(float2*)(g_h + (size_t)(row0 + 8) * 64 + c) = v1;
        } else if (c < 68) {
            int sc = c - 64;
            float2 b2 = *(const float2*)(bs + sc);
            float2 v0 = make_float2(acc[ni][0] + b2.x, acc[ni][1] + b2.y);
            float2 v1 = make_float2(acc[ni][2] + b2.x, acc[ni][3] + b2.y);
            *(float2*)(g_s + (size_t)row0 * 4 + sc)       = v0;
            *(float2*)(g_s + (size_t)(row0 + 8) * 4 + sc) = v1;
        }
    }
}

// ============================================================
// Kernel 2: per-graph kNN (buffered insertion, R9 proven) FUSED
//   with neighbor aggregation. Vote every 2 j, flush at cnt>=3.
//   After the scan each warp aggregates its 32 rows: id/w
//   shfl-broadcast from the owning lane; all gathers of a graph
//   stay inside one CTA -> L1-resident g_h. Outputs bf16 hi/lo
//   aggregates directly (g_id/g_w eliminated).
// ============================================================
#define KNN_CHAIN(v) do { \
    float _v = (v); \
    _Pragma("unroll") \
    for (int _tt = 0; _tt < Kn; _tt++) { \
        float _lo = fminf(_v, lst[_tt]); \
        _v = fmaxf(_v, lst[_tt]); \
        lst[_tt] = _lo; \
    } } while (0)

#define KNN_FLUSH() do { \
    _Pragma("unroll") \
    for (int _k = 0; _k < 4; _k++) { \
        float _bv = (_k == 0) ? b0 : (_k == 1) ? b1 : (_k == 2) ? b2 : b3; \
        if (_k < cnt && _bv < lst[Kn - 1]) KNN_CHAIN(_bv); \
    } \
    cnt = 0; gate = lst[Kn - 1]; } while (0)

#define KNN_STEP(jj) do { \
    float4 mj = sm2[jj]; \
    float tv = fmaf(mj.x, si.x, snj[jj]); \
    tv = fmaf(mj.y, si.y, tv); \
    tv = fmaf(mj.z, si.z, tv); \
    tv = fmaf(mj.w, si.w, tv); \
    float pv = __uint_as_float((__float_as_uint(tv) & 0xFFFFFC00u) | (unsigned)(jj)); \
    if (pv < gate) { b3 = b2; b2 = b1; b1 = b0; b0 = pv; cnt++; } } while (0)

__global__ __launch_bounds__(512) void k_knn()
{
    __shared__ float4 sm2[Lg];   // -2 * s_j
    __shared__ float  snj[Lg];   // |s_j|^2
    int b = blockIdx.x;
    int base = b * Lg;

    for (int i = threadIdx.x; i < Lg; i += blockDim.x) {
        float4 s = *(const float4*)(g_s + (size_t)(base + i) * 4);
        sm2[i] = make_float4(-2.f * s.x, -2.f * s.y, -2.f * s.z, -2.f * s.w);
        snj[i] = s.x * s.x + s.y * s.y + s.z * s.z + s.w * s.w;
    }
    __syncthreads();

    int t = threadIdx.x;
    int lane = t & 31;
    int rloc = blockIdx.y * 512 + t;          // row within graph
    float4 m2i = sm2[rloc];
    float4 si = make_float4(-0.5f * m2i.x, -0.5f * m2i.y, -0.5f * m2i.z, -0.5f * m2i.w);
    float nrm = snj[rloc];

    float lst[Kn];
#pragma unroll
    for (int tt = 0; tt < Kn; tt++) lst[tt] = FLT_MAX;

    float b0 = 0.f, b1 = 0.f, b2 = 0.f, b3 = 0.f;
    int cnt = 0;
    float gate = FLT_MAX;

#pragma unroll 4
    for (int j = 0; j < Lg; j += 2) {
        KNN_STEP(j);
        KNN_STEP(j + 1);
        if (__any_sync(0xffffffffu, cnt >= 3)) KNN_FLUSH();
    }
    KNN_FLUSH();

    // recover winners: exact d2 -> weights; ids kept GLOBAL
    int   oid[Kn];
    float ow [Kn];
#pragma unroll
    for (int tt = 0; tt < Kn; tt++) {
        int j = (int)(__float_as_uint(lst[tt]) & 1023u);
        float4 mj = sm2[j];
        float tv = fmaf(mj.x, si.x, snj[j]);
        tv = fmaf(mj.y, si.y, tv);
        tv = fmaf(mj.z, si.z, tv);
        tv = fmaf(mj.w, si.w, tv);
        float d2 = fmaxf(nrm + tv, 0.f);
        oid[tt] = base + j;
        ow [tt] = __expf(-10.f * d2);
    }

    // ---- fused aggregation: warp handles its 32 rows ----
    int wrow0 = base + blockIdx.y * 512 + (t >> 5) * 32;   // global node of lane 0
#pragma unroll 1
    for (int l = 0; l < 32; l++) {
        float s0 = 0.f, s1 = 0.f, m0 = -FLT_MAX, m1 = -FLT_MAX;
#pragma unroll
        for (int nb = 0; nb < Kn; nb++) {
            int   id = __shfl_sync(0xffffffffu, oid[nb], l);
            float wt = __shfl_sync(0xffffffffu, ow[nb], l);
            float v0 = __ldg(&g_h[(size_t)id * 64 + lane])      * wt;
            float v1 = __ldg(&g_h[(size_t)id * 64 + 32 + lane]) * wt;
            s0 += v0;  s1 += v1;
            m0 = fmaxf(m0, v0);  m1 = fmaxf(m1, v1);
        }
        size_t bidx = (size_t)(wrow0 + l) * 128;
        float vals[4] = { s0 * (1.f / 16.f), s1 * (1.f / 16.f), m0, m1 };
        int   cols[4] = { lane, 32 + lane, 64 + lane, 96 + lane };
#pragma unroll
        for (int q = 0; q < 4; q++) {
            __nv_bfloat16 h, lo;
            split_bf(vals[q], h, lo);
            g_ahi[bidx + cols[q]] = h;
            g_alo[bidx + cols[q]] = lo;
        }
    }
}

// ============================================================
// Kernel 4: out = relu([x|agg] @ W_out + b_out)  (R8 core +
//   register-prefetched A stream: next chunk's A LDGs fly
//   during the MMA section).
// ============================================================
#define APITCH 40

__global__ __launch_bounds__(256) void k_out(
    const float* __restrict__ bout,
    float* __restrict__ out)
{
    __shared__ __nv_bfloat16 Ahi_s[128][APITCH];
    __shared__ __nv_bfloat16 Alo_s[128][APITCH];
    __shared__ __nv_bfloat16 Bhi_s[128][APITCH];
    __shared__ __nv_bfloat16 Blo_s[128][APITCH];

    int t = threadIdx.x;
    int wid = t >> 5, lane = t & 31;
    int warp_m = wid & 1;
    int warp_n = wid >> 1;
    int block_row = blockIdx.x * 128;

    float acc[4][4][4];
#pragma unroll
    for (int mi = 0; mi < 4; mi++)
#pragma unroll
        for (int ni = 0; ni < 4; ni++)
#pragma unroll
            for (int r = 0; r < 4; r++) acc[mi][ni][r] = 0.f;

    int lg = lane >> 3, lr = lane & 7;
    int a_row_off = (lg & 1) * 8 + lr;
    int a_col_off = (lg >> 1) * 8;
    int b_row_off = (lg >> 1) * 8 + lr;
    int b_col_off = (lg & 1) * 8;

    uint32_t sbAhi = smem_u32(&Ahi_s[0][0]);
    uint32_t sbAlo = smem_u32(&Alo_s[0][0]);
    uint32_t sbBhi = smem_u32(&Bhi_s[0][0]);
    uint32_t sbBlo = smem_u32(&Blo_s[0][0]);

    // A-task coords for this thread (2 tasks of uint4)
    int ar[2], aq[2];
#pragma unroll
    for (int it = 0; it < 2; it++) {
        int task = t + it * 256;
        ar[it] = task >> 2;  aq[it] = task & 3;
    }

    uint4 pAh[2], pAl[2];
    auto loadA = [&](int kc) {
        const __nv_bfloat16* sh = ((kc < 4) ? g_xhi : g_ahi) + (kc & 3) * 32;
        const __nv_bfloat16* sl = ((kc < 4) ? g_xlo : g_alo) + (kc & 3) * 32;
#pragma unroll
        for (int it = 0; it < 2; it++) {
            size_t goff = (size_t)(block_row + ar[it]) * 128 + aq[it] * 8;
            pAh[it] = __ldg((const uint4*)(sh + goff));
            pAl[it] = __ldg((const uint4*)(sl + goff));
        }
    };

    loadA(0);

    for (int kc = 0; kc < 8; kc++) {
        // commit prefetched A to smem
#pragma unroll
        for (int it = 0; it < 2; it++) {
            *(uint4*)&Ahi_s[ar[it]][aq[it] * 8] = pAh[it];
            *(uint4*)&Alo_s[ar[it]][aq[it] * 8] = pAl[it];
        }
        // B (L2-hot): direct load
#pragma unroll
        for (int it = 0; it < 2; it++) {
            int task = t + it * 256;
            int n = task >> 2, q = task & 3;
            *(uint4*)&Bhi_s[n][q * 8] = __ldg((const uint4*)(g_Bhi + n * 256 + kc * 32 + q * 8));
            *(uint4*)&Blo_s[n][q * 8] = __ldg((const uint4*)(g_Blo + n * 256 + kc * 32 + q * 8));
        }
        __syncthreads();

        if (kc < 7) loadA(kc + 1);     // overlap with MMAs below

#pragma unroll
        for (int ks = 0; ks < 2; ks++) {
            uint32_t a[4][4], bhi[4][2], blo[4][2];
#pragma unroll
            for (int np = 0; np < 2; np++) {
                uint32_t addr = sbBhi +
                    ((warp_n * 32 + np * 16 + b_row_off) * APITCH + ks * 16 + b_col_off) * 2;
                LDSM_X4(bhi[np * 2][0], bhi[np * 2][1],
                        bhi[np * 2 + 1][0], bhi[np * 2 + 1][1], addr);
                addr = sbBlo +
                    ((warp_n * 32 + np * 16 + b_row_off) * APITCH + ks * 16 + b_col_off) * 2;
                LDSM_X4(blo[np * 2][0], blo[np * 2][1],
                        blo[np * 2 + 1][0], blo[np * 2 + 1][1], addr);
            }
#pragma unroll
            for (int mi = 0; mi < 4; mi++) {
                uint32_t addr = sbAhi +
                    ((warp_m * 64 + mi * 16 + a_row_off) * APITCH + ks * 16 + a_col_off) * 2;
                LDSM_X4(a[mi][0], a[mi][1], a[mi][2], a[mi][3], addr);
            }
#pragma unroll
            for (int mi = 0; mi < 4; mi++)
#pragma unroll
                for (int ni = 0; ni < 4; ni++) {
                    MMA16816(acc[mi][ni], a[mi], bhi[ni]);
                    MMA16816(acc[mi][ni], a[mi], blo[ni]);
                }
#pragma unroll
            for (int mi = 0; mi < 4; mi++) {
                uint32_t addr = sbAlo +
                    ((warp_m * 64 + mi * 16 + a_row_off) * APITCH + ks * 16 + a_col_off) * 2;
                LDSM_X4(a[mi][0], a[mi][1], a[mi][2], a[mi][3], addr);
            }
#pragma unroll
            for (int mi = 0; mi < 4; mi++)
#pragma unroll
                for (int ni = 0; ni < 4; ni++)
                    MMA16816(acc[mi][ni], a[mi], bhi[ni]);
        }
        __syncthreads();
    }

    int qrow = lane >> 2, qcol = (lane & 3) * 2;
    float2 bias2[4];
#pragma unroll
    for (int ni = 0; ni < 4; ni++)
        bias2[ni] = *(const float2*)(bout + warp_n * 32 + ni * 8 + qcol);

#pragma unroll
    for (int mi = 0; mi < 4; mi++) {
        int row0 = block_row + warp_m * 64 + mi * 16 + qrow;
#pragma unroll
        for (int ni = 0; ni < 4; ni++) {
            int col = warp_n * 32 + ni * 8 + qcol;
            float2 v0, v1;
            v0.x = fmaxf(acc[mi][ni][0] + bias2[ni].x, 0.f);
            v0.y = fmaxf(acc[mi][ni][1] + bias2[ni].y, 0.f);
            v1.x = fmaxf(acc[mi][ni][2] + bias2[ni].x, 0.f);
            v1.y = fmaxf(acc[mi][ni][3] + bias2[ni].y, 0.f);
            *(float2*)(out + (size_t)row0 * 128 + col)       = v0;
            *(float2*)(out + (size_t)(row0 + 8) * 128 + col) = v1;
        }
    }
}

// ============================================================
extern "C" void kernel_launch(void* const* d_in, const int* in_sizes, int n_in,
                              void* d_out, int out_size)
{
    const float* x    = (const float*)d_in[0];
    const float* Ws   = (const float*)d_in[1];
    const float* bs   = (const float*)d_in[2];
    const float* Wh   = (const float*)d_in[3];
    const float* bh   = (const float*)d_in[4];
    const float* Wout = (const float*)d_in[5];
    const float* bout = (const float*)d_in[6];
    float* out = (float*)d_out;

    k_wcvt<<<64, 512>>>(Wout, Ws, Wh);
    k_embed<<<Ntot / 64, 256>>>(x, bs, bh);
    k_knn<<<dim3(Bg, 2), 512>>>();
    k_out<<<Ntot / 128, 256>>>(bout, out);
}